// round 7
// baseline (speedup 1.0000x reference)
#include <cuda_runtime.h>
#include <cuda_bf16.h>
#include <cstdint>

#define NCLS    4
#define MAXV    512
#define NROW    2048
#define NANCH   4096
#define DIMF    128
#define NPIX    262144
#define PERBV   131072
#define QSZ     5000
#define NQTOT   (NCLS * QSZ)
#define NBIN    4096
#define CANDMAX 4096
#define NSEL    8          // 0-3 pixel classes, 4-7 queue classes
#define NTILEPAIRS 528     // 32*33/2

// ---------------- device scratch ----------------
__device__ int                g_hist[NSEL * NBIN];
__device__ int                g_T[NSEL];
__device__ int                g_candCnt[NSEL];
__device__ unsigned long long g_cand[NSEL][CANDMAX];
__device__ __nv_bfloat16      g_Xhi[NANCH * DIMF];
__device__ __nv_bfloat16      g_Xlo[NANCH * DIMF];
__device__ float              g_pm[32][NANCH];      // per (coltile, row): rowmax*10
__device__ float              g_ps[32][NANCH];      // per (coltile, row): sum exp
__device__ float              g_pos[NANCH * 1024];  // raw positive dots
__device__ float              g_rowloss[NANCH];

// ---------------- helpers ----------------
__device__ __forceinline__ uint32_t smem_u32(const void* p) {
    uint32_t a;
    asm("{ .reg .u64 t; cvta.to.shared.u64 t, %1; cvt.u32.u64 %0, t; }" : "=r"(a) : "l"(p));
    return a;
}
__device__ __forceinline__ void ldsm4(uint32_t* r, uint32_t addr) {
    asm volatile("ldmatrix.sync.aligned.m8n8.x4.shared.b16 {%0,%1,%2,%3}, [%4];"
                 : "=r"(r[0]), "=r"(r[1]), "=r"(r[2]), "=r"(r[3]) : "r"(addr));
}
__device__ __forceinline__ void mma_bf16(float* c, const uint32_t* a, uint32_t b0, uint32_t b1) {
    asm volatile("mma.sync.aligned.m16n8k16.row.col.f32.bf16.bf16.f32 "
                 "{%0,%1,%2,%3}, {%4,%5,%6,%7}, {%8,%9}, {%0,%1,%2,%3};"
                 : "+f"(c[0]), "+f"(c[1]), "+f"(c[2]), "+f"(c[3])
                 : "r"(a[0]), "r"(a[1]), "r"(a[2]), "r"(a[3]), "r"(b0), "r"(b1));
}
__device__ __forceinline__ int score_bin(float s) {
    int b = (int)(s * (float)NBIN);
    b = b < 0 ? 0 : b;
    return b > NBIN - 1 ? NBIN - 1 : b;
}

// ---------------- selection ----------------
__global__ void k_zero() {
    int i = blockIdx.x * blockDim.x + threadIdx.x;
    if (i < NSEL * NBIN) g_hist[i] = 0;
    if (i < NSEL) { g_candCnt[i] = 0; g_T[i] = 0; }
}

// fused pixel + queue histogram
__global__ void k_histall(const int* __restrict__ labels, const float* __restrict__ scores,
                          const float* __restrict__ qs) {
    int i = blockIdx.x * blockDim.x + threadIdx.x;
    if (i < NPIX) {
        atomicAdd(&g_hist[labels[i] * NBIN + score_bin(scores[i])], 1);
    } else if (i < NPIX + NQTOT) {
        int j = i - NPIX;
        atomicAdd(&g_hist[(4 + j / QSZ) * NBIN + score_bin(qs[j])], 1);
    }
}

// parallel threshold: per class, largest bin b with suffix_inclusive(b) >= MAXV
#define TH_THREADS 512
#define TH_CH      (NBIN / TH_THREADS)   // 8 bins per thread
__global__ void __launch_bounds__(TH_THREADS) k_thresh() {
    __shared__ int sh[NBIN];
    __shared__ int csum[TH_THREADS];
    int c = blockIdx.x, t = threadIdx.x;
    for (int i = t; i < NBIN; i += TH_THREADS) sh[i] = g_hist[c * NBIN + i];
    __syncthreads();
    int s = 0;
    int* h = &sh[t * TH_CH];
#pragma unroll
    for (int u = 0; u < TH_CH; ++u) s += h[u];
    csum[t] = s;
    __syncthreads();
    for (int o = 1; o < TH_THREADS; o <<= 1) {
        int v = (t + o < TH_THREADS) ? csum[t + o] : 0;
        __syncthreads();
        csum[t] += v;
        __syncthreads();
    }
    int above = (t + 1 < TH_THREADS) ? csum[t + 1] : 0;
    if (above < MAXV && csum[t] >= MAXV) {
        int running = above;
#pragma unroll
        for (int u = TH_CH - 1; u >= 0; --u) {
            running += h[u];
            if (running >= MAXV) { g_T[c] = t * TH_CH + u; break; }
        }
    }
}

// fused pixel + queue candidate compaction
__global__ void k_compactall(const int* __restrict__ labels, const float* __restrict__ scores,
                             const float* __restrict__ qs) {
    int i = blockIdx.x * blockDim.x + threadIdx.x;
    if (i < NPIX) {
        int c = labels[i];
        float s = scores[i];
        if (score_bin(s) >= g_T[c]) {
            int pos = atomicAdd(&g_candCnt[c], 1);
            if (pos < CANDMAX)
                g_cand[c][pos] = ((unsigned long long)__float_as_uint(s) << 32)
                               | (unsigned int)(~(unsigned int)i);
        }
    } else if (i < NPIX + NQTOT) {
        int j = i - NPIX;
        int c = 4 + j / QSZ;
        int id = j % QSZ;
        float s = qs[j];
        if (score_bin(s) >= g_T[c]) {
            int pos = atomicAdd(&g_candCnt[c], 1);
            if (pos < CANDMAX)
                g_cand[c][pos] = ((unsigned long long)__float_as_uint(s) << 32)
                               | (unsigned int)(~(unsigned int)id);
        }
    }
}

// fused exact rank-select + gather + bf16 split. One block per selection class.
__global__ void __launch_bounds__(1024) k_selgather(const float* __restrict__ feats,
                                                    const float* __restrict__ pq) {
    __shared__ unsigned long long sk[CANDMAX];
    __shared__ int sidx[MAXV];
    int c = blockIdx.x, t = threadIdx.x;
    int n = g_candCnt[c];
    if (n > CANDMAX) n = CANDMAX;
    for (int i = t; i < n; i += 1024) sk[i] = g_cand[c][i];
    __syncthreads();
    for (int i = t; i < n; i += 1024) {
        unsigned long long k = sk[i];
        int rank = 0;
        for (int j = 0; j < n; ++j) rank += (sk[j] > k);
        if (rank < MAXV)
            sidx[rank] = (int)(~(unsigned int)(k & 0xFFFFFFFFull));
    }
    __syncthreads();

    int rowbase = (c < 4) ? c * 512 : NROW + (c - 4) * 512;
    for (int idx = t; idx < 512 * DIMF; idx += 1024) {
        int slot = idx >> 7, k = idx & 127;
        float v;
        if (c < 4) {
            int p  = sidx[slot];
            int bv = p >> 17;
            int off = p & (PERBV - 1);
            v = feats[(size_t)bv * DIMF * PERBV + (size_t)k * PERBV + off];
        } else {
            int q = sidx[slot];
            v = pq[((size_t)(c - 4) * QSZ + q) * DIMF + k];
        }
        __nv_bfloat16 hi = __float2bfloat16(v);
        __nv_bfloat16 lo = __float2bfloat16(v - __bfloat162float(hi));
        int r = rowbase + slot;
        g_Xhi[r * DIMF + k] = hi;
        g_Xlo[r * DIMF + k] = lo;
    }
}

// ---------------- fused symmetric GEMM + softmax partials ----------------
#define SMEM_DYN (4 * 32768)
__global__ void __launch_bounds__(256, 1) k_gemm() {
    extern __shared__ char dsm[];
    __shared__ float sP[4][128];
    __shared__ float sM[128];
    int t = threadIdx.x, lane = t & 31, w = t >> 5;
    int wm = w & 1, wn = w >> 1;               // warp tile 64(m) x 32(n)
    int gID = lane >> 2, tig = lane & 3;

    // triangular decode: block L -> (bi, bj), bj >= bi
    int L = blockIdx.x, bi = 0;
    while (L >= 32 - bi) { L -= 32 - bi; ++bi; }
    int bj = bi + L;
    uint32_t sbase = smem_u32(dsm);

    // ---- load 4 tiles to swizzled smem ----
    const __nv_bfloat16* srcs[4] = {
        g_Xhi + (size_t)bi * 128 * DIMF, g_Xlo + (size_t)bi * 128 * DIMF,
        g_Xhi + (size_t)bj * 128 * DIMF, g_Xlo + (size_t)bj * 128 * DIMF };
#pragma unroll
    for (int tl = 0; tl < 4; ++tl) {
        const uint4* src = (const uint4*)srcs[tl];
        char* dst = dsm + tl * 32768;
#pragma unroll
        for (int it = 0; it < 8; ++it) {
            int idx = t + it * 256;            // 2048 chunks of 16B
            int row = idx >> 4, ch = idx & 15;
            uint4 v = src[idx];
            *(uint4*)(dst + row * 256 + ((ch ^ (row & 7)) << 4)) = v;
        }
    }
    __syncthreads();

    // ---- mma mainloop ----
    float c[4][4][4];
#pragma unroll
    for (int mf = 0; mf < 4; ++mf)
#pragma unroll
        for (int nf = 0; nf < 4; ++nf)
#pragma unroll
            for (int u = 0; u < 4; ++u) c[mf][nf][u] = 0.f;

    int q = lane >> 3, rowin = lane & 7;
    int rA_in = rowin + (q & 1) * 8;
    int rB_in = rowin + (q >> 1) * 8;
    int cA_add = q >> 1, cB_add = q & 1;

#pragma unroll
    for (int term = 0; term < 3; ++term) {
        uint32_t Ab = sbase + (term == 2 ? 32768 : 0);
        uint32_t Bb = sbase + (term == 1 ? 98304 : 65536);
#pragma unroll
        for (int k0 = 0; k0 < 8; ++k0) {
            uint32_t a[4][4];
#pragma unroll
            for (int mf = 0; mf < 4; ++mf) {
                int row = wm * 64 + mf * 16 + rA_in;
                int ch = 2 * k0 + cA_add;
                ldsm4(a[mf], Ab + row * 256 + ((ch ^ (row & 7)) << 4));
            }
            uint32_t b[2][4];
#pragma unroll
            for (int nf2 = 0; nf2 < 2; ++nf2) {
                int row = wn * 32 + nf2 * 16 + rB_in;
                int ch = 2 * k0 + cB_add;
                ldsm4(b[nf2], Bb + row * 256 + ((ch ^ (row & 7)) << 4));
            }
#pragma unroll
            for (int mf = 0; mf < 4; ++mf)
#pragma unroll
                for (int nf = 0; nf < 4; ++nf)
                    mma_bf16(c[mf][nf], a[mf], b[nf >> 1][(nf & 1) * 2], b[nf >> 1][(nf & 1) * 2 + 1]);
        }
    }

    int sameclass;
    {
        int rc = (bi < 16) ? (bi >> 2) : ((bi - 16) >> 2);
        int cc = (bj < 16) ? (bj >> 2) : ((bj - 16) >> 2);
        sameclass = (rc == cc);
    }

    // ---- row path: partials for rows of bi over cols of bj ----
#pragma unroll
    for (int mf = 0; mf < 4; ++mf)
#pragma unroll
        for (int rs = 0; rs < 2; ++rs) {
            int rl = wm * 64 + mf * 16 + gID + rs * 8;
            float mx = -3.4e38f;
#pragma unroll
            for (int nf = 0; nf < 4; ++nf)
                mx = fmaxf(mx, fmaxf(c[mf][nf][2 * rs], c[mf][nf][2 * rs + 1]));
            mx = fmaxf(mx, __shfl_xor_sync(0xffffffffu, mx, 1));
            mx = fmaxf(mx, __shfl_xor_sync(0xffffffffu, mx, 2));
            if (tig == 0) sP[wn][rl] = mx;
        }
    __syncthreads();
    if (t < 128) sM[t] = fmaxf(fmaxf(sP[0][t], sP[1][t]), fmaxf(sP[2][t], sP[3][t]));
    __syncthreads();
#pragma unroll
    for (int mf = 0; mf < 4; ++mf)
#pragma unroll
        for (int rs = 0; rs < 2; ++rs) {
            int rl = wm * 64 + mf * 16 + gID + rs * 8;
            float M10 = sM[rl] * 10.0f;
            float s = 0.f;
#pragma unroll
            for (int nf = 0; nf < 4; ++nf)
                s += __expf(fmaf(c[mf][nf][2 * rs], 10.0f, -M10))
                   + __expf(fmaf(c[mf][nf][2 * rs + 1], 10.0f, -M10));
            s += __shfl_xor_sync(0xffffffffu, s, 1);
            s += __shfl_xor_sync(0xffffffffu, s, 2);
            if (tig == 0) sP[wn][rl] = s;
        }
    __syncthreads();
    if (t < 128) {
        g_pm[bj][bi * 128 + t] = sM[t] * 10.0f;
        g_ps[bj][bi * 128 + t] = sP[0][t] + sP[1][t] + sP[2][t] + sP[3][t];
    }
    __syncthreads();

    // ---- column path: partials for rows of bj over cols of bi (bi<bj) ----
    if (bj > bi) {
#pragma unroll
        for (int nf = 0; nf < 4; ++nf)
#pragma unroll
            for (int v = 0; v < 2; ++v) {
                float mx = -3.4e38f;
#pragma unroll
                for (int mf = 0; mf < 4; ++mf)
                    mx = fmaxf(mx, fmaxf(c[mf][nf][v], c[mf][nf][2 + v]));
                mx = fmaxf(mx, __shfl_xor_sync(0xffffffffu, mx, 4));
                mx = fmaxf(mx, __shfl_xor_sync(0xffffffffu, mx, 8));
                mx = fmaxf(mx, __shfl_xor_sync(0xffffffffu, mx, 16));
                int cl = wn * 32 + nf * 8 + 2 * tig + v;
                if (gID == 0) sP[wm][cl] = mx;
            }
        __syncthreads();
        if (t < 128) sM[t] = fmaxf(sP[0][t], sP[1][t]);
        __syncthreads();
#pragma unroll
        for (int nf = 0; nf < 4; ++nf)
#pragma unroll
            for (int v = 0; v < 2; ++v) {
                int cl = wn * 32 + nf * 8 + 2 * tig + v;
                float M10 = sM[cl] * 10.0f;
                float s = 0.f;
#pragma unroll
                for (int mf = 0; mf < 4; ++mf)
                    s += __expf(fmaf(c[mf][nf][v], 10.0f, -M10))
                       + __expf(fmaf(c[mf][nf][2 + v], 10.0f, -M10));
                s += __shfl_xor_sync(0xffffffffu, s, 4);
                s += __shfl_xor_sync(0xffffffffu, s, 8);
                s += __shfl_xor_sync(0xffffffffu, s, 16);
                if (gID == 0) sP[wm][cl] = s;
            }
        __syncthreads();
        if (t < 128) {
            g_pm[bi][bj * 128 + t] = sM[t] * 10.0f;
            g_ps[bi][bj * 128 + t] = sP[0][t] + sP[1][t];
        }
    }

    // ---- positive dumps ----
    if (sameclass) {
        int pidx = (bj < 16) ? (bj & 3) : (4 + (bj & 3));
#pragma unroll
        for (int mf = 0; mf < 4; ++mf)
#pragma unroll
            for (int rs = 0; rs < 2; ++rs) {
                int row = bi * 128 + wm * 64 + mf * 16 + gID + rs * 8;
                float* dst = g_pos + (size_t)row * 1024 + pidx * 128;
#pragma unroll
                for (int nf = 0; nf < 4; ++nf) {
                    int col = wn * 32 + nf * 8 + 2 * tig;
                    *(float2*)(dst + col) = make_float2(c[mf][nf][2 * rs], c[mf][nf][2 * rs + 1]);
                }
            }
        if (bj > bi) {
            // transposed dump for rows of bj, staged through smem for coalescing
            float* smT = (float*)dsm;      // [128][132] floats
            __syncthreads();
#pragma unroll
            for (int mf = 0; mf < 4; ++mf)
#pragma unroll
                for (int nf = 0; nf < 4; ++nf)
#pragma unroll
                    for (int u = 0; u < 4; ++u) {
                        int row = wm * 64 + mf * 16 + gID + (u >> 1) * 8;
                        int col = wn * 32 + nf * 8 + 2 * tig + (u & 1);
                        smT[col * 132 + row] = c[mf][nf][u];
                    }
            __syncthreads();
            int pidxT = (bi < 16) ? (bi & 3) : (4 + (bi & 3));
#pragma unroll
            for (int it = 0; it < 16; ++it) {
                int idx = t + it * 256;        // 4096 float4 chunks
                int r2 = idx >> 5, q4 = idx & 31;
                float4 v = *(float4*)&smT[r2 * 132 + q4 * 4];
                *(float4*)&g_pos[(size_t)(bj * 128 + r2) * 1024 + pidxT * 128 + q4 * 4] = v;
            }
        }
    }
}

// ---------------- final per-row loss ----------------
__global__ void __launch_bounds__(128) k_loss() {
    __shared__ float red[128];
    int i = blockIdx.x, t = threadIdx.x;
    int c = (i < NROW) ? (i >> 9) : ((i - NROW) >> 9);

    red[t] = (t < 32) ? g_pm[t][i] : -3.4e38f;
    __syncthreads();
    for (int o = 64; o > 0; o >>= 1) { if (t < o) red[t] = fmaxf(red[t], red[t + o]); __syncthreads(); }
    float M = red[0];
    __syncthreads();

    red[t] = (t < 32) ? g_ps[t][i] * __expf(g_pm[t][i] - M) : 0.f;
    __syncthreads();
    for (int o = 64; o > 0; o >>= 1) { if (t < o) red[t] += red[t + o]; __syncthreads(); }
    float S_all = red[0];
    __syncthreads();

    float lp[8]; int jj[8];
    float sp = 0.f;
#pragma unroll
    for (int u = 0; u < 8; ++u) {
        int qq = t + u * 128;
        int j = (qq < 512) ? c * 512 + qq : NROW + c * 512 + (qq - 512);
        jj[u] = j;
        float d = g_pos[(size_t)i * 1024 + qq];
        lp[u] = fmaf(d, 10.0f, -M);
        if (j != i) sp += __expf(lp[u]);
    }
    red[t] = sp;
    __syncthreads();
    for (int o = 64; o > 0; o >>= 1) { if (t < o) red[t] += red[t + o]; __syncthreads(); }
    float NS = S_all - red[0];
    __syncthreads();

    float ps = 0.f;
#pragma unroll
    for (int u = 0; u < 8; ++u)
        if (jj[u] != i)
            ps += lp[u] - __logf(__expf(lp[u]) + NS + 1e-10f);
    red[t] = ps;
    __syncthreads();
    for (int o = 64; o > 0; o >>= 1) { if (t < o) red[t] += red[t + o]; __syncthreads(); }

    if (t == 0)
        g_rowloss[i] = -(0.1f / 0.07f) * red[0] / (1023.0f + 1e-10f);
}

__global__ void k_reduce(float* __restrict__ out) {
    __shared__ float sh[1024];
    int t = threadIdx.x;
    sh[t] = g_rowloss[t] + g_rowloss[t + 1024] + g_rowloss[t + 2048] + g_rowloss[t + 3072];
    __syncthreads();
    for (int o = 512; o > 0; o >>= 1) { if (t < o) sh[t] += sh[t + o]; __syncthreads(); }
    if (t == 0) out[0] = sh[0] / 4096.0f;
}

// ---------------- launch ----------------
extern "C" void kernel_launch(void* const* d_in, const int* in_sizes, int n_in,
                              void* d_out, int out_size) {
    const float* feats      = (const float*)d_in[0];
    const int*   labels     = (const int*)  d_in[1];
    const float* pixel_q    = (const float*)d_in[2];
    const float* pix_scores = (const float*)d_in[3];
    const float* q_scores   = (const float*)d_in[4];
    float* out = (float*)d_out;

    cudaFuncSetAttribute(k_gemm, cudaFuncAttributeMaxDynamicSharedMemorySize, SMEM_DYN);

    int histN = NPIX + NQTOT;
    k_zero      <<<(NSEL * NBIN + 255) / 256, 256>>>();
    k_histall   <<<(histN + 255) / 256, 256>>>(labels, pix_scores, q_scores);
    k_thresh    <<<NSEL, TH_THREADS>>>();
    k_compactall<<<(histN + 255) / 256, 256>>>(labels, pix_scores, q_scores);
    k_selgather <<<NSEL, 1024>>>(feats, pixel_q);
    k_gemm      <<<NTILEPAIRS, 256, SMEM_DYN>>>();
    k_loss      <<<NANCH, 128>>>();
    k_reduce    <<<1, 1024>>>(out);
}

// round 9
// speedup vs baseline: 1.4323x; 1.4323x over previous
#include <cuda_runtime.h>
#include <cuda_bf16.h>
#include <cstdint>

#define NCLS    4
#define MAXV    512
#define NROW    2048
#define NANCH   4096
#define DIMF    128
#define NPIX    262144
#define PERBV   131072
#define QSZ     5000
#define NQTOT   (NCLS * QSZ)
#define NBIN    4096
#define CANDMAX 4096
#define NSEL    8          // 0-3 pixel classes, 4-7 queue classes
#define NTILEPAIRS 528     // 32*33/2

// ---------------- device scratch ----------------
__device__ int                g_hist[NSEL * NBIN];
__device__ int                g_T[NSEL];
__device__ int                g_candCnt[NSEL];
__device__ unsigned long long g_cand[NSEL][CANDMAX];
__device__ int                g_sel[NSEL][MAXV];
__device__ __nv_bfloat16      g_Xhi[NANCH * DIMF];
__device__ __nv_bfloat16      g_Xlo[NANCH * DIMF];
__device__ float              g_pm[32][NANCH];      // per (coltile, row): rowmax*10
__device__ float              g_ps[32][NANCH];      // per (coltile, row): sum exp
__device__ float              g_pos[NANCH * 1024];  // raw positive dots
__device__ float              g_rowloss[NANCH];

// ---------------- helpers ----------------
__device__ __forceinline__ uint32_t smem_u32(const void* p) {
    uint32_t a;
    asm("{ .reg .u64 t; cvta.to.shared.u64 t, %1; cvt.u32.u64 %0, t; }" : "=r"(a) : "l"(p));
    return a;
}
__device__ __forceinline__ void ldsm4(uint32_t* r, uint32_t addr) {
    asm volatile("ldmatrix.sync.aligned.m8n8.x4.shared.b16 {%0,%1,%2,%3}, [%4];"
                 : "=r"(r[0]), "=r"(r[1]), "=r"(r[2]), "=r"(r[3]) : "r"(addr));
}
__device__ __forceinline__ void mma_bf16(float* c, const uint32_t* a, uint32_t b0, uint32_t b1) {
    asm volatile("mma.sync.aligned.m16n8k16.row.col.f32.bf16.bf16.f32 "
                 "{%0,%1,%2,%3}, {%4,%5,%6,%7}, {%8,%9}, {%0,%1,%2,%3};"
                 : "+f"(c[0]), "+f"(c[1]), "+f"(c[2]), "+f"(c[3])
                 : "r"(a[0]), "r"(a[1]), "r"(a[2]), "r"(a[3]), "r"(b0), "r"(b1));
}
__device__ __forceinline__ int score_bin(float s) {
    int b = (int)(s * (float)NBIN);
    b = b < 0 ? 0 : b;
    return b > NBIN - 1 ? NBIN - 1 : b;
}

// ---------------- selection ----------------
__global__ void k_zero() {
    int i = blockIdx.x * blockDim.x + threadIdx.x;
    if (i < NSEL * NBIN) g_hist[i] = 0;
    if (i < NSEL) { g_candCnt[i] = 0; g_T[i] = 0; }
}

// fused pixel + queue histogram
__global__ void k_histall(const int* __restrict__ labels, const float* __restrict__ scores,
                          const float* __restrict__ qs) {
    int i = blockIdx.x * blockDim.x + threadIdx.x;
    if (i < NPIX) {
        atomicAdd(&g_hist[labels[i] * NBIN + score_bin(scores[i])], 1);
    } else if (i < NPIX + NQTOT) {
        int j = i - NPIX;
        atomicAdd(&g_hist[(4 + j / QSZ) * NBIN + score_bin(qs[j])], 1);
    }
}

// parallel threshold: per class, largest bin b with suffix_inclusive(b) >= MAXV
#define TH_THREADS 512
#define TH_CH      (NBIN / TH_THREADS)   // 8 bins per thread
__global__ void __launch_bounds__(TH_THREADS) k_thresh() {
    __shared__ int sh[NBIN];
    __shared__ int csum[TH_THREADS];
    int c = blockIdx.x, t = threadIdx.x;
    for (int i = t; i < NBIN; i += TH_THREADS) sh[i] = g_hist[c * NBIN + i];
    __syncthreads();
    int s = 0;
    int* h = &sh[t * TH_CH];
#pragma unroll
    for (int u = 0; u < TH_CH; ++u) s += h[u];
    csum[t] = s;
    __syncthreads();
    for (int o = 1; o < TH_THREADS; o <<= 1) {
        int v = (t + o < TH_THREADS) ? csum[t + o] : 0;
        __syncthreads();
        csum[t] += v;
        __syncthreads();
    }
    int above = (t + 1 < TH_THREADS) ? csum[t + 1] : 0;
    if (above < MAXV && csum[t] >= MAXV) {
        int running = above;
#pragma unroll
        for (int u = TH_CH - 1; u >= 0; --u) {
            running += h[u];
            if (running >= MAXV) { g_T[c] = t * TH_CH + u; break; }
        }
    }
}

// fused pixel + queue candidate compaction
__global__ void k_compactall(const int* __restrict__ labels, const float* __restrict__ scores,
                             const float* __restrict__ qs) {
    int i = blockIdx.x * blockDim.x + threadIdx.x;
    if (i < NPIX) {
        int c = labels[i];
        float s = scores[i];
        if (score_bin(s) >= g_T[c]) {
            int pos = atomicAdd(&g_candCnt[c], 1);
            if (pos < CANDMAX)
                g_cand[c][pos] = ((unsigned long long)__float_as_uint(s) << 32)
                               | (unsigned int)(~(unsigned int)i);
        }
    } else if (i < NPIX + NQTOT) {
        int j = i - NPIX;
        int c = 4 + j / QSZ;
        int id = j % QSZ;
        float s = qs[j];
        if (score_bin(s) >= g_T[c]) {
            int pos = atomicAdd(&g_candCnt[c], 1);
            if (pos < CANDMAX)
                g_cand[c][pos] = ((unsigned long long)__float_as_uint(s) << 32)
                               | (unsigned int)(~(unsigned int)id);
        }
    }
}

// exact rank-select per class (8 blocks) -> g_sel
__global__ void __launch_bounds__(1024) k_ranksel() {
    __shared__ unsigned long long sk[CANDMAX];
    int c = blockIdx.x;
    int n = g_candCnt[c];
    if (n > CANDMAX) n = CANDMAX;
    for (int i = threadIdx.x; i < n; i += 1024) sk[i] = g_cand[c][i];
    __syncthreads();
    for (int i = threadIdx.x; i < n; i += 1024) {
        unsigned long long k = sk[i];
        int rank = 0;
        for (int j = 0; j < n; ++j) rank += (sk[j] > k);
        if (rank < MAXV)
            g_sel[c][rank] = (int)(~(unsigned int)(k & 0xFFFFFFFFull));
    }
}

// full-chip gather + bf16 split (one scattered load per thread -> max MLP)
__global__ void k_gather(const float* __restrict__ feats, const float* __restrict__ pq) {
    int r = blockIdx.x;
    int k = threadIdx.x;   // 0..127
    float v;
    if (r < NROW) {
        int c = r >> 9, slot = r & 511;
        int p  = g_sel[c][slot];
        int bv = p >> 17;
        int off = p & (PERBV - 1);
        v = feats[(size_t)bv * DIMF * PERBV + (size_t)k * PERBV + off];
    } else {
        int rr = r - NROW;
        int c = rr >> 9, slot = rr & 511;
        int q = g_sel[4 + c][slot];
        v = pq[((size_t)c * QSZ + q) * DIMF + k];
    }
    __nv_bfloat16 hi = __float2bfloat16(v);
    __nv_bfloat16 lo = __float2bfloat16(v - __bfloat162float(hi));
    g_Xhi[r * DIMF + k] = hi;
    g_Xlo[r * DIMF + k] = lo;
}

// ---------------- fused symmetric GEMM + softmax partials ----------------
#define SMEM_DYN (4 * 32768)
__global__ void __launch_bounds__(256, 1) k_gemm() {
    extern __shared__ char dsm[];
    __shared__ float sP[4][128];
    __shared__ float sM[128];
    int t = threadIdx.x, lane = t & 31, w = t >> 5;
    int wm = w & 1, wn = w >> 1;               // warp tile 64(m) x 32(n)
    int gID = lane >> 2, tig = lane & 3;

    // triangular decode: block L -> (bi, bj), bj >= bi
    int L = blockIdx.x, bi = 0;
    while (L >= 32 - bi) { L -= 32 - bi; ++bi; }
    int bj = bi + L;
    uint32_t sbase = smem_u32(dsm);

    // ---- load 4 tiles to swizzled smem ----
    const __nv_bfloat16* srcs[4] = {
        g_Xhi + (size_t)bi * 128 * DIMF, g_Xlo + (size_t)bi * 128 * DIMF,
        g_Xhi + (size_t)bj * 128 * DIMF, g_Xlo + (size_t)bj * 128 * DIMF };
#pragma unroll
    for (int tl = 0; tl < 4; ++tl) {
        const uint4* src = (const uint4*)srcs[tl];
        char* dst = dsm + tl * 32768;
#pragma unroll
        for (int it = 0; it < 8; ++it) {
            int idx = t + it * 256;            // 2048 chunks of 16B
            int row = idx >> 4, ch = idx & 15;
            uint4 v = src[idx];
            *(uint4*)(dst + row * 256 + ((ch ^ (row & 7)) << 4)) = v;
        }
    }
    __syncthreads();

    // ---- mma mainloop ----
    float c[4][4][4];
#pragma unroll
    for (int mf = 0; mf < 4; ++mf)
#pragma unroll
        for (int nf = 0; nf < 4; ++nf)
#pragma unroll
            for (int u = 0; u < 4; ++u) c[mf][nf][u] = 0.f;

    int q = lane >> 3, rowin = lane & 7;
    int rA_in = rowin + (q & 1) * 8;
    int rB_in = rowin + (q >> 1) * 8;
    int cA_add = q >> 1, cB_add = q & 1;

#pragma unroll
    for (int term = 0; term < 3; ++term) {
        uint32_t Ab = sbase + (term == 2 ? 32768 : 0);
        uint32_t Bb = sbase + (term == 1 ? 98304 : 65536);
#pragma unroll
        for (int k0 = 0; k0 < 8; ++k0) {
            uint32_t a[4][4];
#pragma unroll
            for (int mf = 0; mf < 4; ++mf) {
                int row = wm * 64 + mf * 16 + rA_in;
                int ch = 2 * k0 + cA_add;
                ldsm4(a[mf], Ab + row * 256 + ((ch ^ (row & 7)) << 4));
            }
            uint32_t b[2][4];
#pragma unroll
            for (int nf2 = 0; nf2 < 2; ++nf2) {
                int row = wn * 32 + nf2 * 16 + rB_in;
                int ch = 2 * k0 + cB_add;
                ldsm4(b[nf2], Bb + row * 256 + ((ch ^ (row & 7)) << 4));
            }
#pragma unroll
            for (int mf = 0; mf < 4; ++mf)
#pragma unroll
                for (int nf = 0; nf < 4; ++nf)
                    mma_bf16(c[mf][nf], a[mf], b[nf >> 1][(nf & 1) * 2], b[nf >> 1][(nf & 1) * 2 + 1]);
        }
    }

    int sameclass;
    {
        int rc = (bi < 16) ? (bi >> 2) : ((bi - 16) >> 2);
        int cc = (bj < 16) ? (bj >> 2) : ((bj - 16) >> 2);
        sameclass = (rc == cc);
    }

    // ---- row path: partials for rows of bi over cols of bj ----
#pragma unroll
    for (int mf = 0; mf < 4; ++mf)
#pragma unroll
        for (int rs = 0; rs < 2; ++rs) {
            int rl = wm * 64 + mf * 16 + gID + rs * 8;
            float mx = -3.4e38f;
#pragma unroll
            for (int nf = 0; nf < 4; ++nf)
                mx = fmaxf(mx, fmaxf(c[mf][nf][2 * rs], c[mf][nf][2 * rs + 1]));
            mx = fmaxf(mx, __shfl_xor_sync(0xffffffffu, mx, 1));
            mx = fmaxf(mx, __shfl_xor_sync(0xffffffffu, mx, 2));
            if (tig == 0) sP[wn][rl] = mx;
        }
    __syncthreads();
    if (t < 128) sM[t] = fmaxf(fmaxf(sP[0][t], sP[1][t]), fmaxf(sP[2][t], sP[3][t]));
    __syncthreads();
#pragma unroll
    for (int mf = 0; mf < 4; ++mf)
#pragma unroll
        for (int rs = 0; rs < 2; ++rs) {
            int rl = wm * 64 + mf * 16 + gID + rs * 8;
            float M10 = sM[rl] * 10.0f;
            float s = 0.f;
#pragma unroll
            for (int nf = 0; nf < 4; ++nf)
                s += __expf(fmaf(c[mf][nf][2 * rs], 10.0f, -M10))
                   + __expf(fmaf(c[mf][nf][2 * rs + 1], 10.0f, -M10));
            s += __shfl_xor_sync(0xffffffffu, s, 1);
            s += __shfl_xor_sync(0xffffffffu, s, 2);
            if (tig == 0) sP[wn][rl] = s;
        }
    __syncthreads();
    if (t < 128) {
        g_pm[bj][bi * 128 + t] = sM[t] * 10.0f;
        g_ps[bj][bi * 128 + t] = sP[0][t] + sP[1][t] + sP[2][t] + sP[3][t];
    }
    __syncthreads();

    // ---- column path: partials for rows of bj over cols of bi (bi<bj) ----
    if (bj > bi) {
#pragma unroll
        for (int nf = 0; nf < 4; ++nf)
#pragma unroll
            for (int v = 0; v < 2; ++v) {
                float mx = -3.4e38f;
#pragma unroll
                for (int mf = 0; mf < 4; ++mf)
                    mx = fmaxf(mx, fmaxf(c[mf][nf][v], c[mf][nf][2 + v]));
                mx = fmaxf(mx, __shfl_xor_sync(0xffffffffu, mx, 4));
                mx = fmaxf(mx, __shfl_xor_sync(0xffffffffu, mx, 8));
                mx = fmaxf(mx, __shfl_xor_sync(0xffffffffu, mx, 16));
                int cl = wn * 32 + nf * 8 + 2 * tig + v;
                if (gID == 0) sP[wm][cl] = mx;
            }
        __syncthreads();
        if (t < 128) sM[t] = fmaxf(sP[0][t], sP[1][t]);
        __syncthreads();
#pragma unroll
        for (int nf = 0; nf < 4; ++nf)
#pragma unroll
            for (int v = 0; v < 2; ++v) {
                int cl = wn * 32 + nf * 8 + 2 * tig + v;
                float M10 = sM[cl] * 10.0f;
                float s = 0.f;
#pragma unroll
                for (int mf = 0; mf < 4; ++mf)
                    s += __expf(fmaf(c[mf][nf][v], 10.0f, -M10))
                       + __expf(fmaf(c[mf][nf][2 + v], 10.0f, -M10));
                s += __shfl_xor_sync(0xffffffffu, s, 4);
                s += __shfl_xor_sync(0xffffffffu, s, 8);
                s += __shfl_xor_sync(0xffffffffu, s, 16);
                if (gID == 0) sP[wm][cl] = s;
            }
        __syncthreads();
        if (t < 128) {
            g_pm[bi][bj * 128 + t] = sM[t] * 10.0f;
            g_ps[bi][bj * 128 + t] = sP[0][t] + sP[1][t];
        }
    }

    // ---- positive dumps ----
    if (sameclass) {
        int pidx = (bj < 16) ? (bj & 3) : (4 + (bj & 3));
#pragma unroll
        for (int mf = 0; mf < 4; ++mf)
#pragma unroll
            for (int rs = 0; rs < 2; ++rs) {
                int row = bi * 128 + wm * 64 + mf * 16 + gID + rs * 8;
                float* dst = g_pos + (size_t)row * 1024 + pidx * 128;
#pragma unroll
                for (int nf = 0; nf < 4; ++nf) {
                    int col = wn * 32 + nf * 8 + 2 * tig;
                    *(float2*)(dst + col) = make_float2(c[mf][nf][2 * rs], c[mf][nf][2 * rs + 1]);
                }
            }
        if (bj > bi) {
            // transposed dump for rows of bj, staged through smem for coalescing
            float* smT = (float*)dsm;      // [128][132] floats
            __syncthreads();
#pragma unroll
            for (int mf = 0; mf < 4; ++mf)
#pragma unroll
                for (int nf = 0; nf < 4; ++nf)
#pragma unroll
                    for (int u = 0; u < 4; ++u) {
                        int row = wm * 64 + mf * 16 + gID + (u >> 1) * 8;
                        int col = wn * 32 + nf * 8 + 2 * tig + (u & 1);
                        smT[col * 132 + row] = c[mf][nf][u];
                    }
            __syncthreads();
            int pidxT = (bi < 16) ? (bi & 3) : (4 + (bi & 3));
#pragma unroll
            for (int it = 0; it < 16; ++it) {
                int idx = t + it * 256;        // 4096 float4 chunks
                int r2 = idx >> 5, q4 = idx & 31;
                float4 v = *(float4*)&smT[r2 * 132 + q4 * 4];
                *(float4*)&g_pos[(size_t)(bj * 128 + r2) * 1024 + pidxT * 128 + q4 * 4] = v;
            }
        }
    }
}

// ---------------- final per-row loss ----------------
__global__ void __launch_bounds__(128) k_loss() {
    __shared__ float red[128];
    int i = blockIdx.x, t = threadIdx.x;
    int c = (i < NROW) ? (i >> 9) : ((i - NROW) >> 9);

    red[t] = (t < 32) ? g_pm[t][i] : -3.4e38f;
    __syncthreads();
    for (int o = 64; o > 0; o >>= 1) { if (t < o) red[t] = fmaxf(red[t], red[t + o]); __syncthreads(); }
    float M = red[0];
    __syncthreads();

    red[t] = (t < 32) ? g_ps[t][i] * __expf(g_pm[t][i] - M) : 0.f;
    __syncthreads();
    for (int o = 64; o > 0; o >>= 1) { if (t < o) red[t] += red[t + o]; __syncthreads(); }
    float S_all = red[0];
    __syncthreads();

    float lp[8]; int jj[8];
    float sp = 0.f;
#pragma unroll
    for (int u = 0; u < 8; ++u) {
        int qq = t + u * 128;
        int j = (qq < 512) ? c * 512 + qq : NROW + c * 512 + (qq - 512);
        jj[u] = j;
        float d = g_pos[(size_t)i * 1024 + qq];
        lp[u] = fmaf(d, 10.0f, -M);
        if (j != i) sp += __expf(lp[u]);
    }
    red[t] = sp;
    __syncthreads();
    for (int o = 64; o > 0; o >>= 1) { if (t < o) red[t] += red[t + o]; __syncthreads(); }
    float NS = S_all - red[0];
    __syncthreads();

    float ps = 0.f;
#pragma unroll
    for (int u = 0; u < 8; ++u)
        if (jj[u] != i)
            ps += lp[u] - __logf(__expf(lp[u]) + NS + 1e-10f);
    red[t] = ps;
    __syncthreads();
    for (int o = 64; o > 0; o >>= 1) { if (t < o) red[t] += red[t + o]; __syncthreads(); }

    if (t == 0)
        g_rowloss[i] = -(0.1f / 0.07f) * red[0] / (1023.0f + 1e-10f);
}

__global__ void k_reduce(float* __restrict__ out) {
    __shared__ float sh[1024];
    int t = threadIdx.x;
    sh[t] = g_rowloss[t] + g_rowloss[t + 1024] + g_rowloss[t + 2048] + g_rowloss[t + 3072];
    __syncthreads();
    for (int o = 512; o > 0; o >>= 1) { if (t < o) sh[t] += sh[t + o]; __syncthreads(); }
    if (t == 0) out[0] = sh[0] / 4096.0f;
}

// ---------------- launch ----------------
extern "C" void kernel_launch(void* const* d_in, const int* in_sizes, int n_in,
                              void* d_out, int out_size) {
    const float* feats      = (const float*)d_in[0];
    const int*   labels     = (const int*)  d_in[1];
    const float* pixel_q    = (const float*)d_in[2];
    const float* pix_scores = (const float*)d_in[3];
    const float* q_scores   = (const float*)d_in[4];
    float* out = (float*)d_out;

    cudaFuncSetAttribute(k_gemm, cudaFuncAttributeMaxDynamicSharedMemorySize, SMEM_DYN);

    int histN = NPIX + NQTOT;
    k_zero      <<<(NSEL * NBIN + 255) / 256, 256>>>();
    k_histall   <<<(histN + 255) / 256, 256>>>(labels, pix_scores, q_scores);
    k_thresh    <<<NSEL, TH_THREADS>>>();
    k_compactall<<<(histN + 255) / 256, 256>>>(labels, pix_scores, q_scores);
    k_ranksel   <<<NSEL, 1024>>>();
    k_gather    <<<NANCH, DIMF>>>(feats, pixel_q);
    k_gemm      <<<NTILEPAIRS, 256, SMEM_DYN>>>();
    k_loss      <<<NANCH, 128>>>();
    k_reduce    <<<1, 1024>>>(out);
}

// round 10
// speedup vs baseline: 1.4996x; 1.0470x over previous
#include <cuda_runtime.h>
#include <cuda_bf16.h>
#include <cstdint>

#define NCLS    4
#define MAXV    512
#define NROW    2048
#define NANCH   4096
#define DIMF    128
#define NPIX    262144
#define PERBV   131072
#define QSZ     5000
#define NQTOT   (NCLS * QSZ)
#define NBIN    4096
#define CANDMAX 4096
#define NSEL    8          // 0-3 pixel classes, 4-7 queue classes
#define NTILEPAIRS 528     // 32*33/2

#if defined(__CUDA_ARCH__)
#define GRID_SYNC() cudaGridDependencySynchronize()
#else
#define GRID_SYNC()
#endif

// ---------------- device scratch ----------------
__device__ int                g_hist[NSEL * NBIN];   // zero at load; self-reset each call
__device__ int                g_T[NSEL];
__device__ int                g_candCnt[NSEL];       // zero at load; self-reset each call
__device__ unsigned long long g_cand[NSEL][CANDMAX];
__device__ int                g_sel[NSEL][MAXV];
__device__ __nv_bfloat16      g_Xhi[NANCH * DIMF];
__device__ __nv_bfloat16      g_Xlo[NANCH * DIMF];
__device__ float              g_pm[32][NANCH];      // per (coltile, row): rowmax*10
__device__ float              g_ps[32][NANCH];      // per (coltile, row): sum exp
__device__ float              g_pos[NANCH * 1024];  // raw positive dots
__device__ float              g_rowloss[NANCH];

// ---------------- helpers ----------------
__device__ __forceinline__ uint32_t smem_u32(const void* p) {
    uint32_t a;
    asm("{ .reg .u64 t; cvta.to.shared.u64 t, %1; cvt.u32.u64 %0, t; }" : "=r"(a) : "l"(p));
    return a;
}
__device__ __forceinline__ void ldsm4(uint32_t* r, uint32_t addr) {
    asm volatile("ldmatrix.sync.aligned.m8n8.x4.shared.b16 {%0,%1,%2,%3}, [%4];"
                 : "=r"(r[0]), "=r"(r[1]), "=r"(r[2]), "=r"(r[3]) : "r"(addr));
}
__device__ __forceinline__ void mma_bf16(float* c, const uint32_t* a, uint32_t b0, uint32_t b1) {
    asm volatile("mma.sync.aligned.m16n8k16.row.col.f32.bf16.bf16.f32 "
                 "{%0,%1,%2,%3}, {%4,%5,%6,%7}, {%8,%9}, {%0,%1,%2,%3};"
                 : "+f"(c[0]), "+f"(c[1]), "+f"(c[2]), "+f"(c[3])
                 : "r"(a[0]), "r"(a[1]), "r"(a[2]), "r"(a[3]), "r"(b0), "r"(b1));
}
__device__ __forceinline__ int score_bin(float s) {
    int b = (int)(s * (float)NBIN);
    b = b < 0 ? 0 : b;
    return b > NBIN - 1 ? NBIN - 1 : b;
}

// ---------------- selection ----------------
// fused pixel + queue histogram
__global__ void k_histall(const int* __restrict__ labels, const float* __restrict__ scores,
                          const float* __restrict__ qs) {
    GRID_SYNC();
    int i = blockIdx.x * blockDim.x + threadIdx.x;
    if (i < NPIX) {
        atomicAdd(&g_hist[labels[i] * NBIN + score_bin(scores[i])], 1);
    } else if (i < NPIX + NQTOT) {
        int j = i - NPIX;
        atomicAdd(&g_hist[(4 + j / QSZ) * NBIN + score_bin(qs[j])], 1);
    }
}

// parallel threshold: per class, largest bin b with suffix_inclusive(b) >= MAXV.
// Also re-zeroes this class's histogram bins for the next call (replay-determinism).
#define TH_THREADS 512
#define TH_CH      (NBIN / TH_THREADS)   // 8 bins per thread
__global__ void __launch_bounds__(TH_THREADS) k_thresh() {
    __shared__ int sh[NBIN];
    __shared__ int csum[TH_THREADS];
    GRID_SYNC();
    int c = blockIdx.x, t = threadIdx.x;
    for (int i = t; i < NBIN; i += TH_THREADS) sh[i] = g_hist[c * NBIN + i];
    __syncthreads();
    // reset for next call (all loads complete past the barrier)
    for (int i = t; i < NBIN; i += TH_THREADS) g_hist[c * NBIN + i] = 0;
    int s = 0;
    int* h = &sh[t * TH_CH];
#pragma unroll
    for (int u = 0; u < TH_CH; ++u) s += h[u];
    csum[t] = s;
    __syncthreads();
    for (int o = 1; o < TH_THREADS; o <<= 1) {
        int v = (t + o < TH_THREADS) ? csum[t + o] : 0;
        __syncthreads();
        csum[t] += v;
        __syncthreads();
    }
    int above = (t + 1 < TH_THREADS) ? csum[t + 1] : 0;
    if (above < MAXV && csum[t] >= MAXV) {
        int running = above;
#pragma unroll
        for (int u = TH_CH - 1; u >= 0; --u) {
            running += h[u];
            if (running >= MAXV) { g_T[c] = t * TH_CH + u; break; }
        }
    }
}

// fused pixel + queue candidate compaction
__global__ void k_compactall(const int* __restrict__ labels, const float* __restrict__ scores,
                             const float* __restrict__ qs) {
    GRID_SYNC();
    int i = blockIdx.x * blockDim.x + threadIdx.x;
    if (i < NPIX) {
        int c = labels[i];
        float s = scores[i];
        if (score_bin(s) >= g_T[c]) {
            int pos = atomicAdd(&g_candCnt[c], 1);
            if (pos < CANDMAX)
                g_cand[c][pos] = ((unsigned long long)__float_as_uint(s) << 32)
                               | (unsigned int)(~(unsigned int)i);
        }
    } else if (i < NPIX + NQTOT) {
        int j = i - NPIX;
        int c = 4 + j / QSZ;
        int id = j % QSZ;
        float s = qs[j];
        if (score_bin(s) >= g_T[c]) {
            int pos = atomicAdd(&g_candCnt[c], 1);
            if (pos < CANDMAX)
                g_cand[c][pos] = ((unsigned long long)__float_as_uint(s) << 32)
                               | (unsigned int)(~(unsigned int)id);
        }
    }
}

// exact rank-select per class (8 blocks) -> g_sel; resets g_candCnt for next call
__global__ void __launch_bounds__(1024) k_ranksel() {
    __shared__ unsigned long long sk[CANDMAX];
    GRID_SYNC();
    int c = blockIdx.x;
    int n = g_candCnt[c];
    if (n > CANDMAX) n = CANDMAX;
    for (int i = threadIdx.x; i < n; i += 1024) sk[i] = g_cand[c][i];
    __syncthreads();
    if (threadIdx.x == 0) g_candCnt[c] = 0;   // reset for next call
    for (int i = threadIdx.x; i < n; i += 1024) {
        unsigned long long k = sk[i];
        int rank = 0;
        for (int j = 0; j < n; ++j) rank += (sk[j] > k);
        if (rank < MAXV)
            g_sel[c][rank] = (int)(~(unsigned int)(k & 0xFFFFFFFFull));
    }
}

// full-chip gather + bf16 split (one scattered load per thread -> max MLP)
__global__ void k_gather(const float* __restrict__ feats, const float* __restrict__ pq) {
    GRID_SYNC();
    int r = blockIdx.x;
    int k = threadIdx.x;   // 0..127
    float v;
    if (r < NROW) {
        int c = r >> 9, slot = r & 511;
        int p  = g_sel[c][slot];
        int bv = p >> 17;
        int off = p & (PERBV - 1);
        v = feats[(size_t)bv * DIMF * PERBV + (size_t)k * PERBV + off];
    } else {
        int rr = r - NROW;
        int c = rr >> 9, slot = rr & 511;
        int q = g_sel[4 + c][slot];
        v = pq[((size_t)c * QSZ + q) * DIMF + k];
    }
    __nv_bfloat16 hi = __float2bfloat16(v);
    __nv_bfloat16 lo = __float2bfloat16(v - __bfloat162float(hi));
    g_Xhi[r * DIMF + k] = hi;
    g_Xlo[r * DIMF + k] = lo;
}

// ---------------- fused symmetric GEMM + softmax partials ----------------
#define SMEM_DYN (4 * 32768)
__global__ void __launch_bounds__(256, 1) k_gemm() {
    extern __shared__ char dsm[];
    __shared__ float sP[4][128];
    __shared__ float sM[128];
    GRID_SYNC();
    int t = threadIdx.x, lane = t & 31, w = t >> 5;
    int wm = w & 1, wn = w >> 1;               // warp tile 64(m) x 32(n)
    int gID = lane >> 2, tig = lane & 3;

    // triangular decode: block L -> (bi, bj), bj >= bi
    int L = blockIdx.x, bi = 0;
    while (L >= 32 - bi) { L -= 32 - bi; ++bi; }
    int bj = bi + L;
    uint32_t sbase = smem_u32(dsm);

    // ---- load 4 tiles to swizzled smem ----
    const __nv_bfloat16* srcs[4] = {
        g_Xhi + (size_t)bi * 128 * DIMF, g_Xlo + (size_t)bi * 128 * DIMF,
        g_Xhi + (size_t)bj * 128 * DIMF, g_Xlo + (size_t)bj * 128 * DIMF };
#pragma unroll
    for (int tl = 0; tl < 4; ++tl) {
        const uint4* src = (const uint4*)srcs[tl];
        char* dst = dsm + tl * 32768;
#pragma unroll
        for (int it = 0; it < 8; ++it) {
            int idx = t + it * 256;            // 2048 chunks of 16B
            int row = idx >> 4, ch = idx & 15;
            uint4 v = src[idx];
            *(uint4*)(dst + row * 256 + ((ch ^ (row & 7)) << 4)) = v;
        }
    }
    __syncthreads();

    // ---- mma mainloop ----
    float c[4][4][4];
#pragma unroll
    for (int mf = 0; mf < 4; ++mf)
#pragma unroll
        for (int nf = 0; nf < 4; ++nf)
#pragma unroll
            for (int u = 0; u < 4; ++u) c[mf][nf][u] = 0.f;

    int q = lane >> 3, rowin = lane & 7;
    int rA_in = rowin + (q & 1) * 8;
    int rB_in = rowin + (q >> 1) * 8;
    int cA_add = q >> 1, cB_add = q & 1;

#pragma unroll
    for (int term = 0; term < 3; ++term) {
        uint32_t Ab = sbase + (term == 2 ? 32768 : 0);
        uint32_t Bb = sbase + (term == 1 ? 98304 : 65536);
#pragma unroll
        for (int k0 = 0; k0 < 8; ++k0) {
            uint32_t a[4][4];
#pragma unroll
            for (int mf = 0; mf < 4; ++mf) {
                int row = wm * 64 + mf * 16 + rA_in;
                int ch = 2 * k0 + cA_add;
                ldsm4(a[mf], Ab + row * 256 + ((ch ^ (row & 7)) << 4));
            }
            uint32_t b[2][4];
#pragma unroll
            for (int nf2 = 0; nf2 < 2; ++nf2) {
                int row = wn * 32 + nf2 * 16 + rB_in;
                int ch = 2 * k0 + cB_add;
                ldsm4(b[nf2], Bb + row * 256 + ((ch ^ (row & 7)) << 4));
            }
#pragma unroll
            for (int mf = 0; mf < 4; ++mf)
#pragma unroll
                for (int nf = 0; nf < 4; ++nf)
                    mma_bf16(c[mf][nf], a[mf], b[nf >> 1][(nf & 1) * 2], b[nf >> 1][(nf & 1) * 2 + 1]);
        }
    }

    int sameclass;
    {
        int rc = (bi < 16) ? (bi >> 2) : ((bi - 16) >> 2);
        int cc = (bj < 16) ? (bj >> 2) : ((bj - 16) >> 2);
        sameclass = (rc == cc);
    }

    // ---- row path: partials for rows of bi over cols of bj ----
#pragma unroll
    for (int mf = 0; mf < 4; ++mf)
#pragma unroll
        for (int rs = 0; rs < 2; ++rs) {
            int rl = wm * 64 + mf * 16 + gID + rs * 8;
            float mx = -3.4e38f;
#pragma unroll
            for (int nf = 0; nf < 4; ++nf)
                mx = fmaxf(mx, fmaxf(c[mf][nf][2 * rs], c[mf][nf][2 * rs + 1]));
            mx = fmaxf(mx, __shfl_xor_sync(0xffffffffu, mx, 1));
            mx = fmaxf(mx, __shfl_xor_sync(0xffffffffu, mx, 2));
            if (tig == 0) sP[wn][rl] = mx;
        }
    __syncthreads();
    if (t < 128) sM[t] = fmaxf(fmaxf(sP[0][t], sP[1][t]), fmaxf(sP[2][t], sP[3][t]));
    __syncthreads();
#pragma unroll
    for (int mf = 0; mf < 4; ++mf)
#pragma unroll
        for (int rs = 0; rs < 2; ++rs) {
            int rl = wm * 64 + mf * 16 + gID + rs * 8;
            float M10 = sM[rl] * 10.0f;
            float s = 0.f;
#pragma unroll
            for (int nf = 0; nf < 4; ++nf)
                s += __expf(fmaf(c[mf][nf][2 * rs], 10.0f, -M10))
                   + __expf(fmaf(c[mf][nf][2 * rs + 1], 10.0f, -M10));
            s += __shfl_xor_sync(0xffffffffu, s, 1);
            s += __shfl_xor_sync(0xffffffffu, s, 2);
            if (tig == 0) sP[wn][rl] = s;
        }
    __syncthreads();
    if (t < 128) {
        g_pm[bj][bi * 128 + t] = sM[t] * 10.0f;
        g_ps[bj][bi * 128 + t] = sP[0][t] + sP[1][t] + sP[2][t] + sP[3][t];
    }
    __syncthreads();

    // ---- column path: partials for rows of bj over cols of bi (bi<bj) ----
    if (bj > bi) {
#pragma unroll
        for (int nf = 0; nf < 4; ++nf)
#pragma unroll
            for (int v = 0; v < 2; ++v) {
                float mx = -3.4e38f;
#pragma unroll
                for (int mf = 0; mf < 4; ++mf)
                    mx = fmaxf(mx, fmaxf(c[mf][nf][v], c[mf][nf][2 + v]));
                mx = fmaxf(mx, __shfl_xor_sync(0xffffffffu, mx, 4));
                mx = fmaxf(mx, __shfl_xor_sync(0xffffffffu, mx, 8));
                mx = fmaxf(mx, __shfl_xor_sync(0xffffffffu, mx, 16));
                int cl = wn * 32 + nf * 8 + 2 * tig + v;
                if (gID == 0) sP[wm][cl] = mx;
            }
        __syncthreads();
        if (t < 128) sM[t] = fmaxf(sP[0][t], sP[1][t]);
        __syncthreads();
#pragma unroll
        for (int nf = 0; nf < 4; ++nf)
#pragma unroll
            for (int v = 0; v < 2; ++v) {
                int cl = wn * 32 + nf * 8 + 2 * tig + v;
                float M10 = sM[cl] * 10.0f;
                float s = 0.f;
#pragma unroll
                for (int mf = 0; mf < 4; ++mf)
                    s += __expf(fmaf(c[mf][nf][v], 10.0f, -M10))
                       + __expf(fmaf(c[mf][nf][2 + v], 10.0f, -M10));
                s += __shfl_xor_sync(0xffffffffu, s, 4);
                s += __shfl_xor_sync(0xffffffffu, s, 8);
                s += __shfl_xor_sync(0xffffffffu, s, 16);
                if (gID == 0) sP[wm][cl] = s;
            }
        __syncthreads();
        if (t < 128) {
            g_pm[bi][bj * 128 + t] = sM[t] * 10.0f;
            g_ps[bi][bj * 128 + t] = sP[0][t] + sP[1][t];
        }
    }

    // ---- positive dumps ----
    if (sameclass) {
        int pidx = (bj < 16) ? (bj & 3) : (4 + (bj & 3));
#pragma unroll
        for (int mf = 0; mf < 4; ++mf)
#pragma unroll
            for (int rs = 0; rs < 2; ++rs) {
                int row = bi * 128 + wm * 64 + mf * 16 + gID + rs * 8;
                float* dst = g_pos + (size_t)row * 1024 + pidx * 128;
#pragma unroll
                for (int nf = 0; nf < 4; ++nf) {
                    int col = wn * 32 + nf * 8 + 2 * tig;
                    *(float2*)(dst + col) = make_float2(c[mf][nf][2 * rs], c[mf][nf][2 * rs + 1]);
                }
            }
        if (bj > bi) {
            // transposed dump for rows of bj, staged through smem for coalescing
            float* smT = (float*)dsm;      // [128][132] floats
            __syncthreads();
#pragma unroll
            for (int mf = 0; mf < 4; ++mf)
#pragma unroll
                for (int nf = 0; nf < 4; ++nf)
#pragma unroll
                    for (int u = 0; u < 4; ++u) {
                        int row = wm * 64 + mf * 16 + gID + (u >> 1) * 8;
                        int col = wn * 32 + nf * 8 + 2 * tig + (u & 1);
                        smT[col * 132 + row] = c[mf][nf][u];
                    }
            __syncthreads();
            int pidxT = (bi < 16) ? (bi & 3) : (4 + (bi & 3));
#pragma unroll
            for (int it = 0; it < 16; ++it) {
                int idx = t + it * 256;        // 4096 float4 chunks
                int r2 = idx >> 5, q4 = idx & 31;
                float4 v = *(float4*)&smT[r2 * 132 + q4 * 4];
                *(float4*)&g_pos[(size_t)(bj * 128 + r2) * 1024 + pidxT * 128 + q4 * 4] = v;
            }
        }
    }
}

// ---------------- final per-row loss ----------------
__global__ void __launch_bounds__(128) k_loss() {
    __shared__ float red[128];
    GRID_SYNC();
    int i = blockIdx.x, t = threadIdx.x;
    int c = (i < NROW) ? (i >> 9) : ((i - NROW) >> 9);

    red[t] = (t < 32) ? g_pm[t][i] : -3.4e38f;
    __syncthreads();
    for (int o = 64; o > 0; o >>= 1) { if (t < o) red[t] = fmaxf(red[t], red[t + o]); __syncthreads(); }
    float M = red[0];
    __syncthreads();

    red[t] = (t < 32) ? g_ps[t][i] * __expf(g_pm[t][i] - M) : 0.f;
    __syncthreads();
    for (int o = 64; o > 0; o >>= 1) { if (t < o) red[t] += red[t + o]; __syncthreads(); }
    float S_all = red[0];
    __syncthreads();

    float lp[8]; int jj[8];
    float sp = 0.f;
#pragma unroll
    for (int u = 0; u < 8; ++u) {
        int qq = t + u * 128;
        int j = (qq < 512) ? c * 512 + qq : NROW + c * 512 + (qq - 512);
        jj[u] = j;
        float d = g_pos[(size_t)i * 1024 + qq];
        lp[u] = fmaf(d, 10.0f, -M);
        if (j != i) sp += __expf(lp[u]);
    }
    red[t] = sp;
    __syncthreads();
    for (int o = 64; o > 0; o >>= 1) { if (t < o) red[t] += red[t + o]; __syncthreads(); }
    float NS = S_all - red[0];
    __syncthreads();

    float ps = 0.f;
#pragma unroll
    for (int u = 0; u < 8; ++u)
        if (jj[u] != i)
            ps += lp[u] - __logf(__expf(lp[u]) + NS + 1e-10f);
    red[t] = ps;
    __syncthreads();
    for (int o = 64; o > 0; o >>= 1) { if (t < o) red[t] += red[t + o]; __syncthreads(); }

    if (t == 0)
        g_rowloss[i] = -(0.1f / 0.07f) * red[0] / (1023.0f + 1e-10f);
}

__global__ void k_reduce(float* __restrict__ out) {
    __shared__ float sh[1024];
    GRID_SYNC();
    int t = threadIdx.x;
    sh[t] = g_rowloss[t] + g_rowloss[t + 1024] + g_rowloss[t + 2048] + g_rowloss[t + 3072];
    __syncthreads();
    for (int o = 512; o > 0; o >>= 1) { if (t < o) sh[t] += sh[t + o]; __syncthreads(); }
    if (t == 0) out[0] = sh[0] / 4096.0f;
}

// ---------------- launch (PDL-chained) ----------------
template <typename F, typename... Args>
static void launch_pdl(F f, dim3 grid, dim3 block, size_t smem, Args... args) {
    cudaLaunchConfig_t cfg = {};
    cfg.gridDim = grid;
    cfg.blockDim = block;
    cfg.dynamicSmemBytes = smem;
    cfg.stream = 0;
    cudaLaunchAttribute at[1];
    at[0].id = cudaLaunchAttributeProgrammaticStreamSerialization;
    at[0].val.programmaticStreamSerializationAllowed = 1;
    cfg.attrs = at;
    cfg.numAttrs = 1;
    cudaLaunchKernelEx(&cfg, f, args...);
}

extern "C" void kernel_launch(void* const* d_in, const int* in_sizes, int n_in,
                              void* d_out, int out_size) {
    const float* feats      = (const float*)d_in[0];
    const int*   labels     = (const int*)  d_in[1];
    const float* pixel_q    = (const float*)d_in[2];
    const float* pix_scores = (const float*)d_in[3];
    const float* q_scores   = (const float*)d_in[4];
    float* out = (float*)d_out;

    cudaFuncSetAttribute(k_gemm, cudaFuncAttributeMaxDynamicSharedMemorySize, SMEM_DYN);

    int histN = NPIX + NQTOT;
    k_histall<<<(histN + 255) / 256, 256>>>(labels, pix_scores, q_scores);
    launch_pdl(k_thresh,    dim3(NSEL), dim3(TH_THREADS), 0);
    launch_pdl(k_compactall, dim3((histN + 255) / 256), dim3(256), 0, labels, pix_scores, q_scores);
    launch_pdl(k_ranksel,   dim3(NSEL), dim3(1024), 0);
    launch_pdl(k_gather,    dim3(NANCH), dim3(DIMF), 0, feats, pixel_q);
    launch_pdl(k_gemm,      dim3(NTILEPAIRS), dim3(256), (size_t)SMEM_DYN);
    launch_pdl(k_loss,      dim3(NANCH), dim3(128), 0);
    launch_pdl(k_reduce,    dim3(1), dim3(1024), 0, out);
}

// round 11
// speedup vs baseline: 1.6601x; 1.1070x over previous
#include <cuda_runtime.h>
#include <cuda_bf16.h>
#include <cstdint>

#define NCLS    4
#define MAXV    512
#define NROW    2048
#define NANCH   4096
#define DIMF    128
#define NPIX    262144
#define PERBV   131072
#define QSZ     5000
#define NQTOT   (NCLS * QSZ)
#define NBIN    4096
#define CANDMAX 4096
#define NSEL    8          // 0-3 pixel classes, 4-7 queue classes
#define NTILEPAIRS 528     // 32*33/2

#if defined(__CUDA_ARCH__)
#define GRID_SYNC() cudaGridDependencySynchronize()
#else
#define GRID_SYNC()
#endif

// ---------------- device scratch ----------------
__device__ int                g_hist[NSEL * NBIN];   // zero at load; self-reset each call
__device__ int                g_T[NSEL];
__device__ int                g_cntHi[NSEL];         // candidates strictly above cut bin
__device__ int                g_selCnt[NSEL];        // auto-in slot counter (self-reset)
__device__ int                g_candCnt[NSEL];       // cut-bin list counter (self-reset)
__device__ unsigned long long g_cand[NSEL][CANDMAX];
__device__ int                g_sel[NSEL][MAXV];
__device__ __nv_bfloat16      g_Xhi[NANCH * DIMF];
__device__ __nv_bfloat16      g_Xlo[NANCH * DIMF];
__device__ float              g_pm[32][NANCH];      // per (coltile, row): rowmax*10
__device__ float              g_ps[32][NANCH];      // per (coltile, row): sum exp
__device__ float              g_pos[NANCH * 1024];  // raw positive dots
__device__ float              g_rowloss[NANCH];

// ---------------- helpers ----------------
__device__ __forceinline__ uint32_t smem_u32(const void* p) {
    uint32_t a;
    asm("{ .reg .u64 t; cvta.to.shared.u64 t, %1; cvt.u32.u64 %0, t; }" : "=r"(a) : "l"(p));
    return a;
}
__device__ __forceinline__ void ldsm4(uint32_t* r, uint32_t addr) {
    asm volatile("ldmatrix.sync.aligned.m8n8.x4.shared.b16 {%0,%1,%2,%3}, [%4];"
                 : "=r"(r[0]), "=r"(r[1]), "=r"(r[2]), "=r"(r[3]) : "r"(addr));
}
__device__ __forceinline__ void mma_bf16(float* c, const uint32_t* a, uint32_t b0, uint32_t b1) {
    asm volatile("mma.sync.aligned.m16n8k16.row.col.f32.bf16.bf16.f32 "
                 "{%0,%1,%2,%3}, {%4,%5,%6,%7}, {%8,%9}, {%0,%1,%2,%3};"
                 : "+f"(c[0]), "+f"(c[1]), "+f"(c[2]), "+f"(c[3])
                 : "r"(a[0]), "r"(a[1]), "r"(a[2]), "r"(a[3]), "r"(b0), "r"(b1));
}
__device__ __forceinline__ int score_bin(float s) {
    int b = (int)(s * (float)NBIN);
    b = b < 0 ? 0 : b;
    return b > NBIN - 1 ? NBIN - 1 : b;
}

// ---------------- selection ----------------
// fused pixel + queue histogram, 4 elements per thread
__global__ void k_histall(const int* __restrict__ labels, const float* __restrict__ scores,
                          const float* __restrict__ qs) {
    GRID_SYNC();
    int base = (blockIdx.x * blockDim.x + threadIdx.x) * 4;
    if (base < NPIX) {
        int4   l4 = *(const int4*)(labels + base);
        float4 s4 = *(const float4*)(scores + base);
        atomicAdd(&g_hist[l4.x * NBIN + score_bin(s4.x)], 1);
        atomicAdd(&g_hist[l4.y * NBIN + score_bin(s4.y)], 1);
        atomicAdd(&g_hist[l4.z * NBIN + score_bin(s4.z)], 1);
        atomicAdd(&g_hist[l4.w * NBIN + score_bin(s4.w)], 1);
    } else if (base < NPIX + NQTOT) {
        int j = base - NPIX;
        float4 s4 = *(const float4*)(qs + j);
        int c = 4 + j / QSZ;     // QSZ=5000, 4-pack may straddle class boundary
        int c2 = 4 + (j + 3) / QSZ;
        if (c == c2) {
            atomicAdd(&g_hist[c * NBIN + score_bin(s4.x)], 1);
            atomicAdd(&g_hist[c * NBIN + score_bin(s4.y)], 1);
            atomicAdd(&g_hist[c * NBIN + score_bin(s4.z)], 1);
            atomicAdd(&g_hist[c * NBIN + score_bin(s4.w)], 1);
        } else {
            const float s[4] = {s4.x, s4.y, s4.z, s4.w};
#pragma unroll
            for (int u = 0; u < 4; ++u)
                atomicAdd(&g_hist[(4 + (j + u) / QSZ) * NBIN + score_bin(s[u])], 1);
        }
    }
}

// parallel threshold: per class, largest bin b with suffix_inclusive(b) >= MAXV.
// Stores cut bin T, count strictly above (cntHi); re-zeroes histogram bins.
#define TH_THREADS 512
#define TH_CH      (NBIN / TH_THREADS)   // 8 bins per thread
__global__ void __launch_bounds__(TH_THREADS) k_thresh() {
    __shared__ int sh[NBIN];
    __shared__ int csum[TH_THREADS];
    GRID_SYNC();
    int c = blockIdx.x, t = threadIdx.x;
    for (int i = t; i < NBIN; i += TH_THREADS) sh[i] = g_hist[c * NBIN + i];
    __syncthreads();
    for (int i = t; i < NBIN; i += TH_THREADS) g_hist[c * NBIN + i] = 0;
    int s = 0;
    int* h = &sh[t * TH_CH];
#pragma unroll
    for (int u = 0; u < TH_CH; ++u) s += h[u];
    csum[t] = s;
    __syncthreads();
    for (int o = 1; o < TH_THREADS; o <<= 1) {
        int v = (t + o < TH_THREADS) ? csum[t + o] : 0;
        __syncthreads();
        csum[t] += v;
        __syncthreads();
    }
    int above = (t + 1 < TH_THREADS) ? csum[t + 1] : 0;
    if (above < MAXV && csum[t] >= MAXV) {
        int running = above;
#pragma unroll
        for (int u = TH_CH - 1; u >= 0; --u) {
            running += h[u];
            if (running >= MAXV) {
                g_T[c] = t * TH_CH + u;
                g_cntHi[c] = running - h[u];   // strictly above cut bin
                break;
            }
        }
    }
}

// fused compaction: bin > T -> direct slot in g_sel; bin == T -> small cut list
__device__ __forceinline__ void compact_one(int c, float s, int idx) {
    int b = score_bin(s);
    int T = g_T[c];
    if (b > T) {
        int slot = atomicAdd(&g_selCnt[c], 1);
        g_sel[c][slot] = idx;
    } else if (b == T) {
        int pos = atomicAdd(&g_candCnt[c], 1);
        if (pos < CANDMAX)
            g_cand[c][pos] = ((unsigned long long)__float_as_uint(s) << 32)
                           | (unsigned int)(~(unsigned int)idx);
    }
}
__global__ void k_compactall(const int* __restrict__ labels, const float* __restrict__ scores,
                             const float* __restrict__ qs) {
    GRID_SYNC();
    int base = (blockIdx.x * blockDim.x + threadIdx.x) * 4;
    if (base < NPIX) {
        int4   l4 = *(const int4*)(labels + base);
        float4 s4 = *(const float4*)(scores + base);
        compact_one(l4.x, s4.x, base + 0);
        compact_one(l4.y, s4.y, base + 1);
        compact_one(l4.z, s4.z, base + 2);
        compact_one(l4.w, s4.w, base + 3);
    } else if (base < NPIX + NQTOT) {
        int j = base - NPIX;
        float4 s4 = *(const float4*)(qs + j);
        const float s[4] = {s4.x, s4.y, s4.z, s4.w};
#pragma unroll
        for (int u = 0; u < 4; ++u)
            compact_one(4 + (j + u) / QSZ, s[u], (j + u) % QSZ);
    }
}

// tiny cut-bin ranking: pick top (MAXV - cntHi) of the cut list
__global__ void __launch_bounds__(256) k_ranksel() {
    __shared__ unsigned long long sk[1024];
    GRID_SYNC();
    int c = blockIdx.x, t = threadIdx.x;
    int n = g_candCnt[c];
    if (n > 1024) n = 1024;
    int hi = g_cntHi[c];
    int need = MAXV - hi;
    for (int i = t; i < n; i += 256) sk[i] = g_cand[c][i];
    __syncthreads();
    if (t == 0) { g_candCnt[c] = 0; g_selCnt[c] = 0; }   // reset for next call
    for (int i = t; i < n; i += 256) {
        unsigned long long k = sk[i];
        int rank = 0;
        for (int j = 0; j < n; ++j) rank += (sk[j] > k);
        if (rank < need)
            g_sel[c][hi + rank] = (int)(~(unsigned int)(k & 0xFFFFFFFFull));
    }
}

// full-chip gather + bf16 split (one scattered load per thread -> max MLP)
__global__ void k_gather(const float* __restrict__ feats, const float* __restrict__ pq) {
    GRID_SYNC();
    int r = blockIdx.x;
    int k = threadIdx.x;   // 0..127
    float v;
    if (r < NROW) {
        int c = r >> 9, slot = r & 511;
        int p  = g_sel[c][slot];
        int bv = p >> 17;
        int off = p & (PERBV - 1);
        v = feats[(size_t)bv * DIMF * PERBV + (size_t)k * PERBV + off];
    } else {
        int rr = r - NROW;
        int c = rr >> 9, slot = rr & 511;
        int q = g_sel[4 + c][slot];
        v = pq[((size_t)c * QSZ + q) * DIMF + k];
    }
    __nv_bfloat16 hi = __float2bfloat16(v);
    __nv_bfloat16 lo = __float2bfloat16(v - __bfloat162float(hi));
    g_Xhi[r * DIMF + k] = hi;
    g_Xlo[r * DIMF + k] = lo;
}

// ---------------- fused symmetric GEMM + softmax partials ----------------
#define SMEM_DYN (4 * 32768)
__global__ void __launch_bounds__(256, 1) k_gemm() {
    extern __shared__ char dsm[];
    __shared__ float sP[4][128];
    __shared__ float sM[128];
    GRID_SYNC();
    int t = threadIdx.x, lane = t & 31, w = t >> 5;
    int wm = w & 1, wn = w >> 1;               // warp tile 64(m) x 32(n)
    int gID = lane >> 2, tig = lane & 3;

    // triangular decode: block L -> (bi, bj), bj >= bi
    int L = blockIdx.x, bi = 0;
    while (L >= 32 - bi) { L -= 32 - bi; ++bi; }
    int bj = bi + L;
    uint32_t sbase = smem_u32(dsm);

    // ---- load 4 tiles to swizzled smem ----
    const __nv_bfloat16* srcs[4] = {
        g_Xhi + (size_t)bi * 128 * DIMF, g_Xlo + (size_t)bi * 128 * DIMF,
        g_Xhi + (size_t)bj * 128 * DIMF, g_Xlo + (size_t)bj * 128 * DIMF };
#pragma unroll
    for (int tl = 0; tl < 4; ++tl) {
        const uint4* src = (const uint4*)srcs[tl];
        char* dst = dsm + tl * 32768;
#pragma unroll
        for (int it = 0; it < 8; ++it) {
            int idx = t + it * 256;            // 2048 chunks of 16B
            int row = idx >> 4, ch = idx & 15;
            uint4 v = src[idx];
            *(uint4*)(dst + row * 256 + ((ch ^ (row & 7)) << 4)) = v;
        }
    }
    __syncthreads();

    // ---- mma mainloop ----
    float c[4][4][4];
#pragma unroll
    for (int mf = 0; mf < 4; ++mf)
#pragma unroll
        for (int nf = 0; nf < 4; ++nf)
#pragma unroll
            for (int u = 0; u < 4; ++u) c[mf][nf][u] = 0.f;

    int q = lane >> 3, rowin = lane & 7;
    int rA_in = rowin + (q & 1) * 8;
    int rB_in = rowin + (q >> 1) * 8;
    int cA_add = q >> 1, cB_add = q & 1;

#pragma unroll
    for (int term = 0; term < 3; ++term) {
        uint32_t Ab = sbase + (term == 2 ? 32768 : 0);
        uint32_t Bb = sbase + (term == 1 ? 98304 : 65536);
#pragma unroll
        for (int k0 = 0; k0 < 8; ++k0) {
            uint32_t a[4][4];
#pragma unroll
            for (int mf = 0; mf < 4; ++mf) {
                int row = wm * 64 + mf * 16 + rA_in;
                int ch = 2 * k0 + cA_add;
                ldsm4(a[mf], Ab + row * 256 + ((ch ^ (row & 7)) << 4));
            }
            uint32_t b[2][4];
#pragma unroll
            for (int nf2 = 0; nf2 < 2; ++nf2) {
                int row = wn * 32 + nf2 * 16 + rB_in;
                int ch = 2 * k0 + cB_add;
                ldsm4(b[nf2], Bb + row * 256 + ((ch ^ (row & 7)) << 4));
            }
#pragma unroll
            for (int mf = 0; mf < 4; ++mf)
#pragma unroll
                for (int nf = 0; nf < 4; ++nf)
                    mma_bf16(c[mf][nf], a[mf], b[nf >> 1][(nf & 1) * 2], b[nf >> 1][(nf & 1) * 2 + 1]);
        }
    }

    int sameclass;
    {
        int rc = (bi < 16) ? (bi >> 2) : ((bi - 16) >> 2);
        int cc = (bj < 16) ? (bj >> 2) : ((bj - 16) >> 2);
        sameclass = (rc == cc);
    }

    // ---- row path: partials for rows of bi over cols of bj ----
#pragma unroll
    for (int mf = 0; mf < 4; ++mf)
#pragma unroll
        for (int rs = 0; rs < 2; ++rs) {
            int rl = wm * 64 + mf * 16 + gID + rs * 8;
            float mx = -3.4e38f;
#pragma unroll
            for (int nf = 0; nf < 4; ++nf)
                mx = fmaxf(mx, fmaxf(c[mf][nf][2 * rs], c[mf][nf][2 * rs + 1]));
            mx = fmaxf(mx, __shfl_xor_sync(0xffffffffu, mx, 1));
            mx = fmaxf(mx, __shfl_xor_sync(0xffffffffu, mx, 2));
            if (tig == 0) sP[wn][rl] = mx;
        }
    __syncthreads();
    if (t < 128) sM[t] = fmaxf(fmaxf(sP[0][t], sP[1][t]), fmaxf(sP[2][t], sP[3][t]));
    __syncthreads();
#pragma unroll
    for (int mf = 0; mf < 4; ++mf)
#pragma unroll
        for (int rs = 0; rs < 2; ++rs) {
            int rl = wm * 64 + mf * 16 + gID + rs * 8;
            float M10 = sM[rl] * 10.0f;
            float s = 0.f;
#pragma unroll
            for (int nf = 0; nf < 4; ++nf)
                s += __expf(fmaf(c[mf][nf][2 * rs], 10.0f, -M10))
                   + __expf(fmaf(c[mf][nf][2 * rs + 1], 10.0f, -M10));
            s += __shfl_xor_sync(0xffffffffu, s, 1);
            s += __shfl_xor_sync(0xffffffffu, s, 2);
            if (tig == 0) sP[wn][rl] = s;
        }
    __syncthreads();
    if (t < 128) {
        g_pm[bj][bi * 128 + t] = sM[t] * 10.0f;
        g_ps[bj][bi * 128 + t] = sP[0][t] + sP[1][t] + sP[2][t] + sP[3][t];
    }
    __syncthreads();

    // ---- column path: partials for rows of bj over cols of bi (bi<bj) ----
    if (bj > bi) {
#pragma unroll
        for (int nf = 0; nf < 4; ++nf)
#pragma unroll
            for (int v = 0; v < 2; ++v) {
                float mx = -3.4e38f;
#pragma unroll
                for (int mf = 0; mf < 4; ++mf)
                    mx = fmaxf(mx, fmaxf(c[mf][nf][v], c[mf][nf][2 + v]));
                mx = fmaxf(mx, __shfl_xor_sync(0xffffffffu, mx, 4));
                mx = fmaxf(mx, __shfl_xor_sync(0xffffffffu, mx, 8));
                mx = fmaxf(mx, __shfl_xor_sync(0xffffffffu, mx, 16));
                int cl = wn * 32 + nf * 8 + 2 * tig + v;
                if (gID == 0) sP[wm][cl] = mx;
            }
        __syncthreads();
        if (t < 128) sM[t] = fmaxf(sP[0][t], sP[1][t]);
        __syncthreads();
#pragma unroll
        for (int nf = 0; nf < 4; ++nf)
#pragma unroll
            for (int v = 0; v < 2; ++v) {
                int cl = wn * 32 + nf * 8 + 2 * tig + v;
                float M10 = sM[cl] * 10.0f;
                float s = 0.f;
#pragma unroll
                for (int mf = 0; mf < 4; ++mf)
                    s += __expf(fmaf(c[mf][nf][v], 10.0f, -M10))
                       + __expf(fmaf(c[mf][nf][2 + v], 10.0f, -M10));
                s += __shfl_xor_sync(0xffffffffu, s, 4);
                s += __shfl_xor_sync(0xffffffffu, s, 8);
                s += __shfl_xor_sync(0xffffffffu, s, 16);
                if (gID == 0) sP[wm][cl] = s;
            }
        __syncthreads();
        if (t < 128) {
            g_pm[bi][bj * 128 + t] = sM[t] * 10.0f;
            g_ps[bi][bj * 128 + t] = sP[0][t] + sP[1][t];
        }
    }

    // ---- positive dumps ----
    if (sameclass) {
        int pidx = (bj < 16) ? (bj & 3) : (4 + (bj & 3));
#pragma unroll
        for (int mf = 0; mf < 4; ++mf)
#pragma unroll
            for (int rs = 0; rs < 2; ++rs) {
                int row = bi * 128 + wm * 64 + mf * 16 + gID + rs * 8;
                float* dst = g_pos + (size_t)row * 1024 + pidx * 128;
#pragma unroll
                for (int nf = 0; nf < 4; ++nf) {
                    int col = wn * 32 + nf * 8 + 2 * tig;
                    *(float2*)(dst + col) = make_float2(c[mf][nf][2 * rs], c[mf][nf][2 * rs + 1]);
                }
            }
        if (bj > bi) {
            // transposed dump for rows of bj, staged through smem for coalescing
            float* smT = (float*)dsm;      // [128][132] floats
            __syncthreads();
#pragma unroll
            for (int mf = 0; mf < 4; ++mf)
#pragma unroll
                for (int nf = 0; nf < 4; ++nf)
#pragma unroll
                    for (int u = 0; u < 4; ++u) {
                        int row = wm * 64 + mf * 16 + gID + (u >> 1) * 8;
                        int col = wn * 32 + nf * 8 + 2 * tig + (u & 1);
                        smT[col * 132 + row] = c[mf][nf][u];
                    }
            __syncthreads();
            int pidxT = (bi < 16) ? (bi & 3) : (4 + (bi & 3));
#pragma unroll
            for (int it = 0; it < 16; ++it) {
                int idx = t + it * 256;        // 4096 float4 chunks
                int r2 = idx >> 5, q4 = idx & 31;
                float4 v = *(float4*)&smT[r2 * 132 + q4 * 4];
                *(float4*)&g_pos[(size_t)(bj * 128 + r2) * 1024 + pidxT * 128 + q4 * 4] = v;
            }
        }
    }
}

// ---------------- final per-row loss ----------------
__global__ void __launch_bounds__(128) k_loss() {
    __shared__ float red[128];
    GRID_SYNC();
    int i = blockIdx.x, t = threadIdx.x;
    int c = (i < NROW) ? (i >> 9) : ((i - NROW) >> 9);

    red[t] = (t < 32) ? g_pm[t][i] : -3.4e38f;
    __syncthreads();
    for (int o = 64; o > 0; o >>= 1) { if (t < o) red[t] = fmaxf(red[t], red[t + o]); __syncthreads(); }
    float M = red[0];
    __syncthreads();

    red[t] = (t < 32) ? g_ps[t][i] * __expf(g_pm[t][i] - M) : 0.f;
    __syncthreads();
    for (int o = 64; o > 0; o >>= 1) { if (t < o) red[t] += red[t + o]; __syncthreads(); }
    float S_all = red[0];
    __syncthreads();

    float lp[8]; int jj[8];
    float sp = 0.f;
#pragma unroll
    for (int u = 0; u < 8; ++u) {
        int qq = t + u * 128;
        int j = (qq < 512) ? c * 512 + qq : NROW + c * 512 + (qq - 512);
        jj[u] = j;
        float d = g_pos[(size_t)i * 1024 + qq];
        lp[u] = fmaf(d, 10.0f, -M);
        if (j != i) sp += __expf(lp[u]);
    }
    red[t] = sp;
    __syncthreads();
    for (int o = 64; o > 0; o >>= 1) { if (t < o) red[t] += red[t + o]; __syncthreads(); }
    float NS = S_all - red[0];
    __syncthreads();

    float ps = 0.f;
#pragma unroll
    for (int u = 0; u < 8; ++u)
        if (jj[u] != i)
            ps += lp[u] - __logf(__expf(lp[u]) + NS + 1e-10f);
    red[t] = ps;
    __syncthreads();
    for (int o = 64; o > 0; o >>= 1) { if (t < o) red[t] += red[t + o]; __syncthreads(); }

    if (t == 0)
        g_rowloss[i] = -(0.1f / 0.07f) * red[0] / (1023.0f + 1e-10f);
}

__global__ void k_reduce(float* __restrict__ out) {
    __shared__ float sh[1024];
    GRID_SYNC();
    int t = threadIdx.x;
    sh[t] = g_rowloss[t] + g_rowloss[t + 1024] + g_rowloss[t + 2048] + g_rowloss[t + 3072];
    __syncthreads();
    for (int o = 512; o > 0; o >>= 1) { if (t < o) sh[t] += sh[t + o]; __syncthreads(); }
    if (t == 0) out[0] = sh[0] / 4096.0f;
}

// ---------------- launch (PDL-chained) ----------------
template <typename F, typename... Args>
static void launch_pdl(F f, dim3 grid, dim3 block, size_t smem, Args... args) {
    cudaLaunchConfig_t cfg = {};
    cfg.gridDim = grid;
    cfg.blockDim = block;
    cfg.dynamicSmemBytes = smem;
    cfg.stream = 0;
    cudaLaunchAttribute at[1];
    at[0].id = cudaLaunchAttributeProgrammaticStreamSerialization;
    at[0].val.programmaticStreamSerializationAllowed = 1;
    cfg.attrs = at;
    cfg.numAttrs = 1;
    cudaLaunchKernelEx(&cfg, f, args...);
}

extern "C" void kernel_launch(void* const* d_in, const int* in_sizes, int n_in,
                              void* d_out, int out_size) {
    const float* feats      = (const float*)d_in[0];
    const int*   labels     = (const int*)  d_in[1];
    const float* pixel_q    = (const float*)d_in[2];
    const float* pix_scores = (const float*)d_in[3];
    const float* q_scores   = (const float*)d_in[4];
    float* out = (float*)d_out;

    cudaFuncSetAttribute(k_gemm, cudaFuncAttributeMaxDynamicSharedMemorySize, SMEM_DYN);

    int vecN = (NPIX + NQTOT) / 4;
    k_histall<<<(vecN + 255) / 256, 256>>>(labels, pix_scores, q_scores);
    launch_pdl(k_thresh,     dim3(NSEL), dim3(TH_THREADS), 0);
    launch_pdl(k_compactall, dim3((vecN + 255) / 256), dim3(256), 0, labels, pix_scores, q_scores);
    launch_pdl(k_ranksel,    dim3(NSEL), dim3(256), 0);
    launch_pdl(k_gather,     dim3(NANCH), dim3(DIMF), 0, feats, pixel_q);
    launch_pdl(k_gemm,       dim3(NTILEPAIRS), dim3(256), (size_t)SMEM_DYN);
    launch_pdl(k_loss,       dim3(NANCH), dim3(128), 0);
    launch_pdl(k_reduce,     dim3(1), dim3(1024), 0, out);
}